// round 2
// baseline (speedup 1.0000x reference)
#include <cuda_runtime.h>

// Problem constants
#define B 4
#define T 4096
#define C 1024
#define H 64

// Scratch for projected q/k/v: [B, T, H] fp32 each (4 MB each)
__device__ float g_k[B * T * H];
__device__ float g_q[B * T * H];
__device__ float g_v[B * T * H];

// ---------------------------------------------------------------------------
// Projection: k/q/v[b,t,h] = sum_c x[b,t,c] * W{k,q,v}[h,c]
// Block tile: 64 rows x 192 cols (Wk|Wq|Wv), K-chunks of 32.
// 256 threads as 16x16; each thread owns a 4x12 register micro-tile.
// ---------------------------------------------------------------------------
__global__ __launch_bounds__(256) void proj_kernel(
    const float* __restrict__ x, const float* __restrict__ Wk,
    const float* __restrict__ Wq, const float* __restrict__ Wv) {
  __shared__ float xs[32][64];    // [k][row]   (transposed for broadcast loads)
  __shared__ float ws[32][192];   // [k][col]   col = 64*sel + h
  const int tid = threadIdx.x;
  const int tx = tid & 15, ty = tid >> 4;
  const int row0 = blockIdx.x * 64;
  const int b = blockIdx.y;
  const int lrow = tid & 63;      // staging: which row/h this thread loads
  const int kg = tid >> 6;        // staging: which k-subgroup (0..3)
  const float* xrow = x + ((size_t)b * T + row0 + lrow) * C;
  const float* wbase[3] = {Wk, Wq, Wv};

  float acc[4][12];
#pragma unroll
  for (int i = 0; i < 4; i++)
#pragma unroll
    for (int j = 0; j < 12; j++) acc[i][j] = 0.f;

  for (int kb = 0; kb < C; kb += 32) {
    // Stage x chunk: 64 rows x 32 k, transposed. Conflict-free STS (lanes span rows).
#pragma unroll
    for (int it = 0; it < 2; it++) {
      int k0 = kg * 8 + it * 4;
      float4 v = *(const float4*)(xrow + kb + k0);
      xs[k0 + 0][lrow] = v.x; xs[k0 + 1][lrow] = v.y;
      xs[k0 + 2][lrow] = v.z; xs[k0 + 3][lrow] = v.w;
    }
    // Stage W chunk: 192 cols x 32 k, transposed.
#pragma unroll
    for (int w = 0; w < 3; w++) {
      const float* wr = wbase[w] + (size_t)lrow * C + kb;
      int cc = w * 64 + lrow;
#pragma unroll
      for (int it = 0; it < 2; it++) {
        int k0 = kg * 8 + it * 4;
        float4 v = *(const float4*)(wr + k0);
        ws[k0 + 0][cc] = v.x; ws[k0 + 1][cc] = v.y;
        ws[k0 + 2][cc] = v.z; ws[k0 + 3][cc] = v.w;
      }
    }
    __syncthreads();
#pragma unroll 4
    for (int k = 0; k < 32; k++) {
      float4 a = *(const float4*)&xs[k][ty * 4];
      float4 b0 = *(const float4*)&ws[k][tx * 12];
      float4 b1 = *(const float4*)&ws[k][tx * 12 + 4];
      float4 b2 = *(const float4*)&ws[k][tx * 12 + 8];
      float av[4] = {a.x, a.y, a.z, a.w};
      float bv[12] = {b0.x, b0.y, b0.z, b0.w, b1.x, b1.y, b1.z, b1.w,
                      b2.x, b2.y, b2.z, b2.w};
#pragma unroll
      for (int i = 0; i < 4; i++)
#pragma unroll
        for (int j = 0; j < 12; j++) acc[i][j] = fmaf(av[i], bv[j], acc[i][j]);
    }
    __syncthreads();
  }

  // Scatter results to g_k / g_q / g_v
#pragma unroll
  for (int i = 0; i < 4; i++) {
    int r = row0 + ty * 4 + i;
#pragma unroll
    for (int j = 0; j < 12; j++) {
      int col = tx * 12 + j;
      int sel = col >> 6;
      int h = col & 63;
      float* op = (sel == 0) ? g_k : (sel == 1) ? g_q : g_v;
      op[((size_t)b * T + r) * H + h] = acc[i][j];
    }
  }
}

// ---------------------------------------------------------------------------
// Flash attention: per block = 64 query rows of one batch.
// Online softmax, fp32. smem: qs (Q, transposed), kp (K transposed, then
// reused for P row-major), vs (V natural). 3 x 16 KB = 48 KB static.
// Long causal rows scheduled first (reversed blockIdx.x) to shrink the tail.
// ---------------------------------------------------------------------------
__global__ __launch_bounds__(256) void attn_kernel(float* __restrict__ out) {
  __shared__ float qs[64][64];  // [h][row]
  __shared__ float kp[64][64];  // phase 1: K [h][col]; phase 2: P [row][col]
  __shared__ float vs[64][64];  // [col(j)][h]
  const int tid = threadIdx.x;
  const int tx = tid & 15, ty = tid >> 4;
  const int qt = (T / 64 - 1) - blockIdx.x;  // longest blocks first
  const int b = blockIdx.y;
  const int q0 = qt * 64;
  const int lcol = tid & 63;
  const int hg = tid >> 6;

  // Load Q tile, transposed into qs[h][row]
  const float* qg = g_q + ((size_t)b * T + q0) * H;
#pragma unroll
  for (int it = 0; it < 4; it++) {
    int h0 = (hg + it * 4) * 4;
    float4 v = *(const float4*)(qg + (size_t)lcol * H + h0);
    qs[h0 + 0][lcol] = v.x; qs[h0 + 1][lcol] = v.y;
    qs[h0 + 2][lcol] = v.z; qs[h0 + 3][lcol] = v.w;
  }

  float m[4], l[4], o[4][4];
#pragma unroll
  for (int i = 0; i < 4; i++) {
    m[i] = -1e30f;
    l[i] = 0.f;
#pragma unroll
    for (int j = 0; j < 4; j++) o[i][j] = 0.f;
  }
  __syncthreads();

  for (int sb = 0; sb <= qt; sb++) {
    const int s0 = sb * 64;
    const float* kg = g_k + ((size_t)b * T + s0) * H;
    const float* vg = g_v + ((size_t)b * T + s0) * H;
    // K tile transposed: kp[h][col]
#pragma unroll
    for (int it = 0; it < 4; it++) {
      int h0 = (hg + it * 4) * 4;
      float4 v = *(const float4*)(kg + (size_t)lcol * H + h0);
      kp[h0 + 0][lcol] = v.x; kp[h0 + 1][lcol] = v.y;
      kp[h0 + 2][lcol] = v.z; kp[h0 + 3][lcol] = v.w;
    }
    // V tile natural: vs[j][h]
#pragma unroll
    for (int it = 0; it < 4; it++) {
      int idx = tid + it * 256;
      int j = idx >> 4, hq = (idx & 15) * 4;
      *(float4*)&vs[j][hq] = *(const float4*)(vg + (size_t)j * H + hq);
    }
    __syncthreads();

    // S = Q K^T  (4x4 per thread)
    float s[4][4];
#pragma unroll
    for (int i = 0; i < 4; i++)
#pragma unroll
      for (int j = 0; j < 4; j++) s[i][j] = 0.f;
#pragma unroll 8
    for (int h = 0; h < 64; h++) {
      float4 a = *(const float4*)&qs[h][ty * 4];
      float4 bb = *(const float4*)&kp[h][tx * 4];
      float av[4] = {a.x, a.y, a.z, a.w};
      float bv[4] = {bb.x, bb.y, bb.z, bb.w};
#pragma unroll
      for (int i = 0; i < 4; i++)
#pragma unroll
        for (int j = 0; j < 4; j++) s[i][j] = fmaf(av[i], bv[j], s[i][j]);
    }
    const float scale = 0.03125f;  // C^-0.5 = 1/32 (reference scales by n_embd!)
    if (sb == qt) {
#pragma unroll
      for (int i = 0; i < 4; i++)
#pragma unroll
        for (int j = 0; j < 4; j++) {
          s[i][j] *= scale;
          if (tx * 4 + j > ty * 4 + i) s[i][j] = -1e30f;
        }
    } else {
#pragma unroll
      for (int i = 0; i < 4; i++)
#pragma unroll
        for (int j = 0; j < 4; j++) s[i][j] *= scale;
    }

    // Online softmax (row state replicated across the 16 tx threads of a row)
#pragma unroll
    for (int i = 0; i < 4; i++) {
      float v = fmaxf(fmaxf(s[i][0], s[i][1]), fmaxf(s[i][2], s[i][3]));
#pragma unroll
      for (int off = 8; off > 0; off >>= 1)
        v = fmaxf(v, __shfl_xor_sync(0xffffffffu, v, off));
      float mn = fmaxf(m[i], v);
      float al = __expf(m[i] - mn);
      m[i] = mn;
      float rs = 0.f;
#pragma unroll
      for (int j = 0; j < 4; j++) {
        s[i][j] = __expf(s[i][j] - mn);
        rs += s[i][j];
      }
#pragma unroll
      for (int off = 8; off > 0; off >>= 1)
        rs += __shfl_xor_sync(0xffffffffu, rs, off);
      l[i] = l[i] * al + rs;
#pragma unroll
      for (int j = 0; j < 4; j++) o[i][j] *= al;
    }
    __syncthreads();  // everyone done reading kp as K

    // Store P row-major into kp: ps[row][col]
#pragma unroll
    for (int i = 0; i < 4; i++)
      *(float4*)&kp[ty * 4 + i][tx * 4] =
          make_float4(s[i][0], s[i][1], s[i][2], s[i][3]);
    __syncthreads();

    // O += P V   (rows ty*4.., h-cols tx*4..)
#pragma unroll 8
    for (int j = 0; j < 64; j++) {
      float4 bb = *(const float4*)&vs[j][tx * 4];
      float av[4] = {kp[ty * 4 + 0][j], kp[ty * 4 + 1][j],
                     kp[ty * 4 + 2][j], kp[ty * 4 + 3][j]};
      float bv[4] = {bb.x, bb.y, bb.z, bb.w};
#pragma unroll
      for (int i = 0; i < 4; i++)
#pragma unroll
        for (int j2 = 0; j2 < 4; j2++) o[i][j2] = fmaf(av[i], bv[j2], o[i][j2]);
    }
    __syncthreads();  // before next iteration overwrites kp/vs
  }

  // Epilogue: normalize and store
  float* op = out + ((size_t)b * T + q0) * H;
#pragma unroll
  for (int i = 0; i < 4; i++) {
    float inv = 1.0f / l[i];
    *(float4*)&op[(size_t)(ty * 4 + i) * H + tx * 4] =
        make_float4(o[i][0] * inv, o[i][1] * inv, o[i][2] * inv, o[i][3] * inv);
  }
}

extern "C" void kernel_launch(void* const* d_in, const int* in_sizes, int n_in,
                              void* d_out, int out_size) {
  (void)in_sizes; (void)n_in; (void)out_size;
  const float* x  = (const float*)d_in[0];
  const float* Wk = (const float*)d_in[1];
  const float* Wq = (const float*)d_in[2];
  const float* Wv = (const float*)d_in[3];
  float* out = (float*)d_out;

  dim3 grid(T / 64, B);
  proj_kernel<<<grid, 256>>>(x, Wk, Wq, Wv);
  attn_kernel<<<grid, 256>>>(out);
}

// round 4
// speedup vs baseline: 1.3155x; 1.3155x over previous
#include <cuda_runtime.h>

// Problem constants
#define B 4
#define T 4096
#define C 1024
#define H 64
#define NCHUNK 4          // max KV chunks per q-tile
#define CHUNK_TILES 16    // 16 tiles of 64 = 1024 keys per chunk

// Scratch for projected q/k/v: [B, T, H] fp32 each (4 MB each)
__device__ float g_k[B * T * H];
__device__ float g_q[B * T * H];
__device__ float g_v[B * T * H];
// Split-KV partials: O unnormalized, per-row running max m and denom l
__device__ float g_opart[B * NCHUNK * T * H];   // 64 MB
__device__ float g_mpart[B * NCHUNK * T];
__device__ float g_lpart[B * NCHUNK * T];

// ---------------------------------------------------------------------------
// Projection: k/q/v[b,t,h] = sum_c x[b,t,c] * W{k,q,v}[h,c]
// (unchanged from R2 — measured at ~80% of fp32 SIMT peak)
// ---------------------------------------------------------------------------
__global__ __launch_bounds__(256) void proj_kernel(
    const float* __restrict__ x, const float* __restrict__ Wk,
    const float* __restrict__ Wq, const float* __restrict__ Wv) {
  __shared__ float xs[32][64];    // [k][row]
  __shared__ float ws[32][192];   // [k][col]   col = 64*sel + h
  const int tid = threadIdx.x;
  const int tx = tid & 15, ty = tid >> 4;
  const int row0 = blockIdx.x * 64;
  const int b = blockIdx.y;
  const int lrow = tid & 63;
  const int kg = tid >> 6;
  const float* xrow = x + ((size_t)b * T + row0 + lrow) * C;
  const float* wbase[3] = {Wk, Wq, Wv};

  float acc[4][12];
#pragma unroll
  for (int i = 0; i < 4; i++)
#pragma unroll
    for (int j = 0; j < 12; j++) acc[i][j] = 0.f;

  for (int kb = 0; kb < C; kb += 32) {
#pragma unroll
    for (int it = 0; it < 2; it++) {
      int k0 = kg * 8 + it * 4;
      float4 v = *(const float4*)(xrow + kb + k0);
      xs[k0 + 0][lrow] = v.x; xs[k0 + 1][lrow] = v.y;
      xs[k0 + 2][lrow] = v.z; xs[k0 + 3][lrow] = v.w;
    }
#pragma unroll
    for (int w = 0; w < 3; w++) {
      const float* wr = wbase[w] + (size_t)lrow * C + kb;
      int cc = w * 64 + lrow;
#pragma unroll
      for (int it = 0; it < 2; it++) {
        int k0 = kg * 8 + it * 4;
        float4 v = *(const float4*)(wr + k0);
        ws[k0 + 0][cc] = v.x; ws[k0 + 1][cc] = v.y;
        ws[k0 + 2][cc] = v.z; ws[k0 + 3][cc] = v.w;
      }
    }
    __syncthreads();
#pragma unroll 4
    for (int k = 0; k < 32; k++) {
      float4 a = *(const float4*)&xs[k][ty * 4];
      float4 b0 = *(const float4*)&ws[k][tx * 12];
      float4 b1 = *(const float4*)&ws[k][tx * 12 + 4];
      float4 b2 = *(const float4*)&ws[k][tx * 12 + 8];
      float av[4] = {a.x, a.y, a.z, a.w};
      float bv[12] = {b0.x, b0.y, b0.z, b0.w, b1.x, b1.y, b1.z, b1.w,
                      b2.x, b2.y, b2.z, b2.w};
#pragma unroll
      for (int i = 0; i < 4; i++)
#pragma unroll
        for (int j = 0; j < 12; j++) acc[i][j] = fmaf(av[i], bv[j], acc[i][j]);
    }
    __syncthreads();
  }

#pragma unroll
  for (int i = 0; i < 4; i++) {
    int r = row0 + ty * 4 + i;
#pragma unroll
    for (int j = 0; j < 12; j++) {
      int col = tx * 12 + j;
      int sel = col >> 6;
      int h = col & 63;
      float* op = (sel == 0) ? g_k : (sel == 1) ? g_q : g_v;
      op[((size_t)b * T + r) * H + h] = acc[i][j];
    }
  }
}

// ---------------------------------------------------------------------------
// Split-KV flash attention partial.
// Block = (q-tile qt, kv-chunk, batch). Computes unnormalized partial
// (O, m, l) over tiles [chunk*16, min(chunk*16+16, qt+1)).
// grid.x reversed so large qt (full 16-step chunks) schedule first.
// ---------------------------------------------------------------------------
__global__ __launch_bounds__(256) void attn_part_kernel() {
  const int qt = (T / 64 - 1) - blockIdx.x;
  const int chunk = blockIdx.y;
  const int b = blockIdx.z;
  const int sb_begin = chunk * CHUNK_TILES;
  const int sb_end = min(sb_begin + CHUNK_TILES, qt + 1);
  if (sb_begin > qt) return;  // uniform early exit, before any barrier

  __shared__ float qs[64][64];  // [h][row]
  __shared__ float kp[64][64];  // K [h][col], then P [row][col]
  __shared__ float vs[64][64];  // [col(j)][h]
  const int tid = threadIdx.x;
  const int tx = tid & 15, ty = tid >> 4;
  const int q0 = qt * 64;
  const int lcol = tid & 63;
  const int hg = tid >> 6;

  const float* qg = g_q + ((size_t)b * T + q0) * H;
#pragma unroll
  for (int it = 0; it < 4; it++) {
    int h0 = (hg + it * 4) * 4;
    float4 v = *(const float4*)(qg + (size_t)lcol * H + h0);
    qs[h0 + 0][lcol] = v.x; qs[h0 + 1][lcol] = v.y;
    qs[h0 + 2][lcol] = v.z; qs[h0 + 3][lcol] = v.w;
  }

  float m[4], l[4], o[4][4];
#pragma unroll
  for (int i = 0; i < 4; i++) {
    m[i] = -1e30f;
    l[i] = 0.f;
#pragma unroll
    for (int j = 0; j < 4; j++) o[i][j] = 0.f;
  }
  __syncthreads();

  for (int sb = sb_begin; sb < sb_end; sb++) {
    const int s0 = sb * 64;
    const float* kg = g_k + ((size_t)b * T + s0) * H;
    const float* vg = g_v + ((size_t)b * T + s0) * H;
#pragma unroll
    for (int it = 0; it < 4; it++) {
      int h0 = (hg + it * 4) * 4;
      float4 v = *(const float4*)(kg + (size_t)lcol * H + h0);
      kp[h0 + 0][lcol] = v.x; kp[h0 + 1][lcol] = v.y;
      kp[h0 + 2][lcol] = v.z; kp[h0 + 3][lcol] = v.w;
    }
#pragma unroll
    for (int it = 0; it < 4; it++) {
      int idx = tid + it * 256;
      int j = idx >> 4, hq = (idx & 15) * 4;
      *(float4*)&vs[j][hq] = *(const float4*)(vg + (size_t)j * H + hq);
    }
    __syncthreads();

    // S = Q K^T  (4x4 per thread)
    float s[4][4];
#pragma unroll
    for (int i = 0; i < 4; i++)
#pragma unroll
      for (int j = 0; j < 4; j++) s[i][j] = 0.f;
#pragma unroll 8
    for (int h = 0; h < 64; h++) {
      float4 a = *(const float4*)&qs[h][ty * 4];
      float4 bb = *(const float4*)&kp[h][tx * 4];
      float av[4] = {a.x, a.y, a.z, a.w};
      float bv[4] = {bb.x, bb.y, bb.z, bb.w};
#pragma unroll
      for (int i = 0; i < 4; i++)
#pragma unroll
        for (int j = 0; j < 4; j++) s[i][j] = fmaf(av[i], bv[j], s[i][j]);
    }
    const float scale = 0.03125f;  // C^-0.5 = 1/32 (reference scales by n_embd)
    if (sb == qt) {
#pragma unroll
      for (int i = 0; i < 4; i++)
#pragma unroll
        for (int j = 0; j < 4; j++) {
          s[i][j] *= scale;
          if (tx * 4 + j > ty * 4 + i) s[i][j] = -1e30f;
        }
    } else {
#pragma unroll
      for (int i = 0; i < 4; i++)
#pragma unroll
        for (int j = 0; j < 4; j++) s[i][j] *= scale;
    }

    // Online softmax (row state replicated across 16 tx threads)
#pragma unroll
    for (int i = 0; i < 4; i++) {
      float v = fmaxf(fmaxf(s[i][0], s[i][1]), fmaxf(s[i][2], s[i][3]));
#pragma unroll
      for (int off = 8; off > 0; off >>= 1)
        v = fmaxf(v, __shfl_xor_sync(0xffffffffu, v, off));
      float mn = fmaxf(m[i], v);
      float al = __expf(m[i] - mn);
      m[i] = mn;
      float rs = 0.f;
#pragma unroll
      for (int j = 0; j < 4; j++) {
        s[i][j] = __expf(s[i][j] - mn);
        rs += s[i][j];
      }
#pragma unroll
      for (int off = 8; off > 0; off >>= 1)
        rs += __shfl_xor_sync(0xffffffffu, rs, off);
      l[i] = l[i] * al + rs;
#pragma unroll
      for (int j = 0; j < 4; j++) o[i][j] *= al;
    }
    __syncthreads();

    // Store P row-major into kp
#pragma unroll
    for (int i = 0; i < 4; i++)
      *(float4*)&kp[ty * 4 + i][tx * 4] =
          make_float4(s[i][0], s[i][1], s[i][2], s[i][3]);
    __syncthreads();

    // O += P V
#pragma unroll 8
    for (int j = 0; j < 64; j++) {
      float4 bb = *(const float4*)&vs[j][tx * 4];
      float av[4] = {kp[ty * 4 + 0][j], kp[ty * 4 + 1][j],
                     kp[ty * 4 + 2][j], kp[ty * 4 + 3][j]};
      float bv[4] = {bb.x, bb.y, bb.z, bb.w};
#pragma unroll
      for (int i = 0; i < 4; i++)
#pragma unroll
        for (int j2 = 0; j2 < 4; j2++) o[i][j2] = fmaf(av[i], bv[j2], o[i][j2]);
    }
    __syncthreads();
  }

  // Write unnormalized partial
  const size_t pbase = ((size_t)b * NCHUNK + chunk) * T + q0;
  float* op = g_opart + pbase * H;
#pragma unroll
  for (int i = 0; i < 4; i++) {
    *(float4*)&op[(size_t)(ty * 4 + i) * H + tx * 4] =
        make_float4(o[i][0], o[i][1], o[i][2], o[i][3]);
    if (tx == 0) {
      g_mpart[pbase + ty * 4 + i] = m[i];
      g_lpart[pbase + ty * 4 + i] = l[i];
    }
  }
}

// ---------------------------------------------------------------------------
// Reduce partials: out[b,t,h] = sum_i e^{m_i-M} O_i / sum_i e^{m_i-M} l_i
// One thread per output element.
// ---------------------------------------------------------------------------
__global__ __launch_bounds__(256) void attn_reduce_kernel(float* __restrict__ out) {
  const size_t idx = (size_t)blockIdx.x * 256 + threadIdx.x;  // b*T*H range
  const int h = idx & (H - 1);
  const size_t bt = idx >> 6;      // b*T + t
  const int t = (int)(bt & (T - 1));
  const int b = (int)(bt >> 12);
  const int qt = t >> 6;
  const int nch = (qt + CHUNK_TILES) / CHUNK_TILES;  // ceil((qt+1)/16)

  float mv[NCHUNK], lv[NCHUNK];
  float M = -1e30f;
#pragma unroll
  for (int c = 0; c < NCHUNK; c++) {
    if (c < nch) {
      size_t pb = ((size_t)b * NCHUNK + c) * T + t;
      mv[c] = g_mpart[pb];
      lv[c] = g_lpart[pb];
      M = fmaxf(M, mv[c]);
    }
  }
  float Osum = 0.f, Lsum = 0.f;
#pragma unroll
  for (int c = 0; c < NCHUNK; c++) {
    if (c < nch) {
      float w = __expf(mv[c] - M);
      size_t pb = ((size_t)b * NCHUNK + c) * T + t;
      Osum += w * g_opart[pb * H + h];
      Lsum += w * lv[c];
    }
  }
  out[idx] = Osum / Lsum;
}

extern "C" void kernel_launch(void* const* d_in, const int* in_sizes, int n_in,
                              void* d_out, int out_size) {
  (void)in_sizes; (void)n_in; (void)out_size;
  const float* x  = (const float*)d_in[0];
  const float* Wk = (const float*)d_in[1];
  const float* Wq = (const float*)d_in[2];
  const float* Wv = (const float*)d_in[3];
  float* out = (float*)d_out;

  dim3 pgrid(T / 64, B);
  proj_kernel<<<pgrid, 256>>>(x, Wk, Wq, Wv);
  dim3 agrid(T / 64, NCHUNK, B);
  attn_part_kernel<<<agrid, 256>>>();
  attn_reduce_kernel<<<(B * T * H) / 256, 256>>>(out);
}

// round 5
// speedup vs baseline: 3.1637x; 2.4049x over previous
#include <cuda_runtime.h>

// Problem constants
#define B 4
#define T 4096
#define C 1024
#define H 64
#define NCHUNK 4          // max KV chunks per q-tile
#define CHUNK_TILES 16    // 16 tiles of 64 = 1024 keys per chunk

// q/k/v stored as tf32 bit patterns (q pre-scaled by C^-0.5)
__device__ unsigned g_k[B * T * H];
__device__ unsigned g_q[B * T * H];
__device__ unsigned g_v[B * T * H];
// Split-KV partials (fp32)
__device__ float g_opart[B * NCHUNK * T * H];
__device__ float g_mpart[B * NCHUNK * T];
__device__ float g_lpart[B * NCHUNK * T];

__device__ __forceinline__ unsigned f2tf(float f) {
  unsigned u;
  asm("cvt.rna.tf32.f32 %0, %1;" : "=r"(u) : "f"(f));
  return u;
}

// D = A(16x8,row) * B(8x8,col) + D, tf32 inputs, fp32 accum
__device__ __forceinline__ void mma_tf32(float c[4], unsigned a0, unsigned a1,
                                         unsigned a2, unsigned a3, unsigned b0,
                                         unsigned b1) {
  asm volatile(
      "mma.sync.aligned.m16n8k8.row.col.f32.tf32.tf32.f32 "
      "{%0,%1,%2,%3}, {%4,%5,%6,%7}, {%8,%9}, {%0,%1,%2,%3};\n"
      : "+f"(c[0]), "+f"(c[1]), "+f"(c[2]), "+f"(c[3])
      : "r"(a0), "r"(a1), "r"(a2), "r"(a3), "r"(b0), "r"(b1));
}

// XOR swizzle within a row of a [rows][COLS] fp32/tf32 tile (COLS=32 or 64)
__device__ __forceinline__ int swz(int col, int row) {
  return (((col >> 2) ^ (row & 7)) << 2) | (col & 3);
}

// ---------------------------------------------------------------------------
// Projection via tf32 mma: 32-row x 192-col tiles, 128 threads (4 warps 2x2).
// Outputs tf32 bits; q pre-scaled by C^-0.5.
// ---------------------------------------------------------------------------
__global__ __launch_bounds__(128) void proj_kernel(
    const float* __restrict__ x, const float* __restrict__ Wk,
    const float* __restrict__ Wq, const float* __restrict__ Wv) {
  __shared__ unsigned xs[32 * 32];   // [row][k] swizzled
  __shared__ unsigned ws[192 * 32];  // [n][k]  swizzled (n = 64*sel + h)
  const int tid = threadIdx.x;
  const int w = tid >> 5, lane = tid & 31, g = lane >> 2, tig = lane & 3;
  const int rw = (w & 1) * 16;        // warp row offset (0/16)
  const int cw = (w >> 1) * 96;       // warp col offset (0/96)
  const int row0 = blockIdx.x * 32;
  const int b = blockIdx.y;
  const float* wbase[3] = {Wk, Wq, Wv};

  float c[12][4];
#pragma unroll
  for (int j = 0; j < 12; j++)
#pragma unroll
    for (int e = 0; e < 4; e++) c[j][e] = 0.f;

  for (int kb = 0; kb < C; kb += 32) {
    // stage x: 32 rows x 32 k
#pragma unroll
    for (int i = tid; i < 256; i += 128) {
      int row = i >> 3, c4 = i & 7;
      float4 v = *(const float4*)(x + ((size_t)b * T + row0 + row) * C + kb + c4 * 4);
      unsigned* d = xs + row * 32 + ((c4 ^ (row & 7)) << 2);
      d[0] = f2tf(v.x); d[1] = f2tf(v.y); d[2] = f2tf(v.z); d[3] = f2tf(v.w);
    }
    // stage W: 192 n x 32 k
#pragma unroll
    for (int i = tid; i < 1536; i += 128) {
      int n = i >> 3, c4 = i & 7;
      float4 v = *(const float4*)(wbase[n >> 6] + (size_t)(n & 63) * C + kb + c4 * 4);
      unsigned* d = ws + n * 32 + ((c4 ^ (n & 7)) << 2);
      d[0] = f2tf(v.x); d[1] = f2tf(v.y); d[2] = f2tf(v.z); d[3] = f2tf(v.w);
    }
    __syncthreads();
#pragma unroll
    for (int kk = 0; kk < 4; kk++) {
      unsigned a0 = xs[(rw + g) * 32 + (((2 * kk) ^ g) << 2 | tig)];
      unsigned a1 = xs[(rw + g + 8) * 32 + (((2 * kk) ^ g) << 2 | tig)];
      unsigned a2 = xs[(rw + g) * 32 + (((2 * kk + 1) ^ g) << 2 | tig)];
      unsigned a3 = xs[(rw + g + 8) * 32 + (((2 * kk + 1) ^ g) << 2 | tig)];
#pragma unroll
      for (int j = 0; j < 12; j++) {
        unsigned b0 = ws[(cw + 8 * j + g) * 32 + (((2 * kk) ^ g) << 2 | tig)];
        unsigned b1 = ws[(cw + 8 * j + g) * 32 + (((2 * kk + 1) ^ g) << 2 | tig)];
        mma_tf32(c[j], a0, a1, a2, a3, b0, b1);
      }
    }
    __syncthreads();
  }

  // epilogue: tf32 bits; q (sel==1) pre-scaled by C^-0.5 = 1/32
  unsigned* outp[3] = {g_k, g_q, g_v};
#pragma unroll
  for (int j = 0; j < 12; j++) {
    int n = cw + 8 * j + 2 * tig;
    int sel = n >> 6, h = n & 63;
    float sc = (sel == 1) ? 0.03125f : 1.0f;
    unsigned* d0 = outp[sel] + ((size_t)b * T + row0 + rw + g) * H + h;
    unsigned* d1 = outp[sel] + ((size_t)b * T + row0 + rw + g + 8) * H + h;
    d0[0] = f2tf(c[j][0] * sc); d0[1] = f2tf(c[j][1] * sc);
    d1[0] = f2tf(c[j][2] * sc); d1[1] = f2tf(c[j][3] * sc);
  }
}

// ---------------------------------------------------------------------------
// Split-KV flash attention with tf32 mma. 128 threads / 4 warps; warp w owns
// S rows [w*16, w*16+16) -> softmax fully warp-local. P aliases K smem.
// ---------------------------------------------------------------------------
__global__ __launch_bounds__(128) void attn_part_kernel() {
  const int qt = (T / 64 - 1) - blockIdx.x;
  const int chunk = blockIdx.y;
  const int b = blockIdx.z;
  const int sb_begin = chunk * CHUNK_TILES;
  const int sb_end = min(sb_begin + CHUNK_TILES, qt + 1);
  if (sb_begin > qt) return;  // uniform exit before any barrier

  __shared__ unsigned sQ[64 * 64];
  __shared__ unsigned sKP[64 * 64];  // K tile, then P tile
  __shared__ unsigned sV[64 * 64];
  const int tid = threadIdx.x;
  const int w = tid >> 5, lane = tid & 31, g = lane >> 2, tig = lane & 3;
  const int rw = w * 16;
  const int q0 = qt * 64;

  // stage Q (already tf32 bits, already scaled)
  const unsigned* qg = g_q + ((size_t)b * T + q0) * H;
#pragma unroll
  for (int i = tid; i < 1024; i += 128) {
    int row = i >> 4, c4 = i & 15;
    *(uint4*)(sQ + row * 64 + ((c4 ^ (row & 7)) << 2)) =
        *(const uint4*)(qg + row * 64 + c4 * 4);
  }

  float m0 = -1e30f, m1 = -1e30f, l0 = 0.f, l1 = 0.f;
  float o[8][4];
#pragma unroll
  for (int j = 0; j < 8; j++)
#pragma unroll
    for (int e = 0; e < 4; e++) o[j][e] = 0.f;
  __syncthreads();

  for (int sb = sb_begin; sb < sb_end; sb++) {
    const unsigned* kg = g_k + ((size_t)b * T + sb * 64) * H;
    const unsigned* vg = g_v + ((size_t)b * T + sb * 64) * H;
#pragma unroll
    for (int i = tid; i < 1024; i += 128) {
      int row = i >> 4, c4 = i & 15;
      int d = row * 64 + ((c4 ^ (row & 7)) << 2);
      *(uint4*)(sKP + d) = *(const uint4*)(kg + row * 64 + c4 * 4);
      *(uint4*)(sV + d) = *(const uint4*)(vg + row * 64 + c4 * 4);
    }
    __syncthreads();

    // S = Q K^T (q pre-scaled)
    float s[8][4];
#pragma unroll
    for (int j = 0; j < 8; j++)
#pragma unroll
      for (int e = 0; e < 4; e++) s[j][e] = 0.f;
#pragma unroll
    for (int kk = 0; kk < 8; kk++) {
      unsigned a0 = sQ[(rw + g) * 64 + (((2 * kk) ^ g) << 2 | tig)];
      unsigned a1 = sQ[(rw + g + 8) * 64 + (((2 * kk) ^ g) << 2 | tig)];
      unsigned a2 = sQ[(rw + g) * 64 + (((2 * kk + 1) ^ g) << 2 | tig)];
      unsigned a3 = sQ[(rw + g + 8) * 64 + (((2 * kk + 1) ^ g) << 2 | tig)];
#pragma unroll
      for (int j = 0; j < 8; j++) {
        unsigned b0 = sKP[(8 * j + g) * 64 + (((2 * kk) ^ g) << 2 | tig)];
        unsigned b1 = sKP[(8 * j + g) * 64 + (((2 * kk + 1) ^ g) << 2 | tig)];
        mma_tf32(s[j], a0, a1, a2, a3, b0, b1);
      }
    }

    // causal mask on diagonal tile
    const int qrow0 = q0 + rw + g, qrow1 = qrow0 + 8;
    if (sb == qt) {
#pragma unroll
      for (int j = 0; j < 8; j++) {
        int c0 = sb * 64 + 8 * j + 2 * tig;
        if (c0 > qrow0) s[j][0] = -1e30f;
        if (c0 + 1 > qrow0) s[j][1] = -1e30f;
        if (c0 > qrow1) s[j][2] = -1e30f;
        if (c0 + 1 > qrow1) s[j][3] = -1e30f;
      }
    }

    // online softmax, rows qrow0 (s[.][0,1]) and qrow1 (s[.][2,3])
    float mx0 = -1e30f, mx1 = -1e30f;
#pragma unroll
    for (int j = 0; j < 8; j++) {
      mx0 = fmaxf(mx0, fmaxf(s[j][0], s[j][1]));
      mx1 = fmaxf(mx1, fmaxf(s[j][2], s[j][3]));
    }
#pragma unroll
    for (int off = 1; off <= 2; off <<= 1) {
      mx0 = fmaxf(mx0, __shfl_xor_sync(0xffffffffu, mx0, off));
      mx1 = fmaxf(mx1, __shfl_xor_sync(0xffffffffu, mx1, off));
    }
    float mn0 = fmaxf(m0, mx0), mn1 = fmaxf(m1, mx1);
    float al0 = __expf(m0 - mn0), al1 = __expf(m1 - mn1);
    m0 = mn0; m1 = mn1;
    float rs0 = 0.f, rs1 = 0.f;
#pragma unroll
    for (int j = 0; j < 8; j++) {
      s[j][0] = __expf(s[j][0] - mn0); rs0 += s[j][0];
      s[j][1] = __expf(s[j][1] - mn0); rs0 += s[j][1];
      s[j][2] = __expf(s[j][2] - mn1); rs1 += s[j][2];
      s[j][3] = __expf(s[j][3] - mn1); rs1 += s[j][3];
    }
#pragma unroll
    for (int off = 1; off <= 2; off <<= 1) {
      rs0 += __shfl_xor_sync(0xffffffffu, rs0, off);
      rs1 += __shfl_xor_sync(0xffffffffu, rs1, off);
    }
    l0 = l0 * al0 + rs0;
    l1 = l1 * al1 + rs1;
#pragma unroll
    for (int j = 0; j < 8; j++) {
      o[j][0] *= al0; o[j][1] *= al0;
      o[j][2] *= al1; o[j][3] *= al1;
    }
    __syncthreads();  // everyone done reading sKP as K

    // P -> sKP (tf32 bits), row-major [qrow][key]
#pragma unroll
    for (int j = 0; j < 8; j++) {
      int cc = 8 * j + 2 * tig;
      sKP[(rw + g) * 64 + swz(cc, g)] = f2tf(s[j][0]);
      sKP[(rw + g) * 64 + swz(cc + 1, g)] = f2tf(s[j][1]);
      sKP[(rw + g + 8) * 64 + swz(cc, g)] = f2tf(s[j][2]);
      sKP[(rw + g + 8) * 64 + swz(cc + 1, g)] = f2tf(s[j][3]);
    }
    __syncthreads();

    // O += P V
#pragma unroll
    for (int kk = 0; kk < 8; kk++) {
      int k0 = 8 * kk;
      unsigned a0 = sKP[(rw + g) * 64 + (((2 * kk) ^ g) << 2 | tig)];
      unsigned a1 = sKP[(rw + g + 8) * 64 + (((2 * kk) ^ g) << 2 | tig)];
      unsigned a2 = sKP[(rw + g) * 64 + (((2 * kk + 1) ^ g) << 2 | tig)];
      unsigned a3 = sKP[(rw + g + 8) * 64 + (((2 * kk + 1) ^ g) << 2 | tig)];
#pragma unroll
      for (int j = 0; j < 8; j++) {
        unsigned b0 = sV[(k0 + tig) * 64 + swz(8 * j + g, k0 + tig)];
        unsigned b1 = sV[(k0 + tig + 4) * 64 + swz(8 * j + g, k0 + tig + 4)];
        mma_tf32(o[j], a0, a1, a2, a3, b0, b1);
      }
    }
    __syncthreads();  // before next staging overwrites sKP/sV
  }

  // write unnormalized partial
  const size_t pbase = ((size_t)b * NCHUNK + chunk) * T + q0;
  float* op = g_opart + pbase * H;
#pragma unroll
  for (int j = 0; j < 8; j++) {
    int cc = 8 * j + 2 * tig;
    *(float2*)&op[(size_t)(rw + g) * H + cc] = make_float2(o[j][0], o[j][1]);
    *(float2*)&op[(size_t)(rw + g + 8) * H + cc] = make_float2(o[j][2], o[j][3]);
  }
  if (tig == 0) {
    g_mpart[pbase + rw + g] = m0;
    g_lpart[pbase + rw + g] = l0;
    g_mpart[pbase + rw + g + 8] = m1;
    g_lpart[pbase + rw + g + 8] = l1;
  }
}

// ---------------------------------------------------------------------------
// Reduce partials: out[b,t,h] = sum_i e^{m_i-M} O_i / sum_i e^{m_i-M} l_i
// ---------------------------------------------------------------------------
__global__ __launch_bounds__(256) void attn_reduce_kernel(float* __restrict__ out) {
  const size_t idx = (size_t)blockIdx.x * 256 + threadIdx.x;
  const int h = idx & (H - 1);
  const size_t bt = idx >> 6;
  const int t = (int)(bt & (T - 1));
  const int b = (int)(bt >> 12);
  const int qt = t >> 6;
  const int nch = (qt + CHUNK_TILES) / CHUNK_TILES;

  float mv[NCHUNK], lv[NCHUNK];
  float M = -1e30f;
#pragma unroll
  for (int c = 0; c < NCHUNK; c++) {
    if (c < nch) {
      size_t pb = ((size_t)b * NCHUNK + c) * T + t;
      mv[c] = g_mpart[pb];
      lv[c] = g_lpart[pb];
      M = fmaxf(M, mv[c]);
    }
  }
  float Osum = 0.f, Lsum = 0.f;
#pragma unroll
  for (int c = 0; c < NCHUNK; c++) {
    if (c < nch) {
      float ww = __expf(mv[c] - M);
      size_t pb = ((size_t)b * NCHUNK + c) * T + t;
      Osum += ww * g_opart[pb * H + h];
      Lsum += ww * lv[c];
    }
  }
  out[idx] = Osum / Lsum;
}

extern "C" void kernel_launch(void* const* d_in, const int* in_sizes, int n_in,
                              void* d_out, int out_size) {
  (void)in_sizes; (void)n_in; (void)out_size;
  const float* x  = (const float*)d_in[0];
  const float* Wk = (const float*)d_in[1];
  const float* Wq = (const float*)d_in[2];
  const float* Wv = (const float*)d_in[3];
  float* out = (float*)d_out;

  dim3 pgrid(T / 32, B);
  proj_kernel<<<pgrid, 128>>>(x, Wk, Wq, Wv);
  dim3 agrid(T / 64, NCHUNK, B);
  attn_part_kernel<<<agrid, 128>>>();
  attn_reduce_kernel<<<(B * T * H) / 256, 256>>>(out);
}

// round 6
// speedup vs baseline: 4.1987x; 1.3272x over previous
#include <cuda_runtime.h>

// Problem constants
#define B 4
#define T 4096
#define C 1024
#define H 64
#define NCHUNK 4          // max KV chunks per q-tile
#define CHUNK_TILES 16    // 16 tiles of 64 = 1024 keys per chunk

// q/k/v stored as tf32 bit patterns (q pre-scaled by C^-0.5)
__device__ unsigned g_k[B * T * H];
__device__ unsigned g_q[B * T * H];
__device__ unsigned g_v[B * T * H];
// Split-KV partials (fp32)
__device__ float g_opart[B * NCHUNK * T * H];
__device__ float g_mpart[B * NCHUNK * T];
__device__ float g_lpart[B * NCHUNK * T];

__device__ __forceinline__ unsigned f2tf(float f) {
  unsigned u;
  asm("cvt.rna.tf32.f32 %0, %1;" : "=r"(u) : "f"(f));
  return u;
}

// D = A(16x8,row) * B(8x8,col) + D, tf32 inputs, fp32 accum
__device__ __forceinline__ void mma_tf32(float c[4], unsigned a0, unsigned a1,
                                         unsigned a2, unsigned a3, unsigned b0,
                                         unsigned b1) {
  asm volatile(
      "mma.sync.aligned.m16n8k8.row.col.f32.tf32.tf32.f32 "
      "{%0,%1,%2,%3}, {%4,%5,%6,%7}, {%8,%9}, {%0,%1,%2,%3};\n"
      : "+f"(c[0]), "+f"(c[1]), "+f"(c[2]), "+f"(c[3])
      : "r"(a0), "r"(a1), "r"(a2), "r"(a3), "r"(b0), "r"(b1));
}

// XOR swizzle within a row of a [rows][COLS] tile (used by attention)
__device__ __forceinline__ int swz(int col, int row) {
  return (((col >> 2) ^ (row & 7)) << 2) | (col & 3);
}

// ---------------------------------------------------------------------------
// Projection via tf32 mma: 64-row x 192-col tiles, 256 threads (8 warps 4x2).
// Padded smem (row stride 36 words -> conflict-free, no xor swizzle).
// Register-prefetch pipeline: LDG chunk kb+1 issued before computing kb.
// Outputs tf32 bits; q pre-scaled by C^-0.5.
// ---------------------------------------------------------------------------
#define PJ_PAD 36  // words per 32-element k-row (32 data + 4 pad)
__global__ __launch_bounds__(256) void proj_kernel(
    const float* __restrict__ x, const float* __restrict__ Wk,
    const float* __restrict__ Wq, const float* __restrict__ Wv) {
  __shared__ unsigned xs[64 * PJ_PAD];   // [row][k] padded
  __shared__ unsigned ws[192 * PJ_PAD];  // [n][k]  padded (n = 64*sel + h)
  const int tid = threadIdx.x;
  const int w = tid >> 5, lane = tid & 31, g = lane >> 2, tig = lane & 3;
  const int rw = (w & 3) * 16;        // warp row offset (0..48)
  const int cw = (w >> 2) * 96;       // warp col offset (0/96)
  const int row0 = blockIdx.x * 64;
  const int b = blockIdx.y;
  const float* wbase[3] = {Wk, Wq, Wv};

  // Staging assignments (fixed per thread):
  // xs: items tid, tid+256 of 512   (row = i>>3, c4 = i&7)
  // ws: items tid + 256*it, it=0..5 (n = i>>3, c4 = i&7)
  const int xrowA = tid >> 3, xc4A = tid & 7;
  const int xrowB = (tid + 256) >> 3, xc4B = tid & 7;
  const float* xsrcA = x + ((size_t)b * T + row0 + xrowA) * C + xc4A * 4;
  const float* xsrcB = x + ((size_t)b * T + row0 + xrowB) * C + xc4B * 4;
  const float* wsrc[6];
  int wn[6], wc4[6];
#pragma unroll
  for (int it = 0; it < 6; it++) {
    int i = tid + 256 * it;
    wn[it] = i >> 3;
    wc4[it] = i & 7;
    wsrc[it] = wbase[wn[it] >> 6] + (size_t)(wn[it] & 63) * C + wc4[it] * 4;
  }

  float c[12][4];
#pragma unroll
  for (int j = 0; j < 12; j++)
#pragma unroll
    for (int e = 0; e < 4; e++) c[j][e] = 0.f;

  // prefetch chunk 0
  float4 px0 = *(const float4*)(xsrcA);
  float4 px1 = *(const float4*)(xsrcB);
  float4 pw[6];
#pragma unroll
  for (int it = 0; it < 6; it++) pw[it] = *(const float4*)(wsrc[it]);

  for (int kb = 0; kb < C; kb += 32) {
    __syncthreads();  // smem free (readers of previous chunk done)
    // store prefetched chunk (rna -> tf32)
    {
      unsigned* d = xs + xrowA * PJ_PAD + xc4A * 4;
      d[0] = f2tf(px0.x); d[1] = f2tf(px0.y); d[2] = f2tf(px0.z); d[3] = f2tf(px0.w);
      d = xs + xrowB * PJ_PAD + xc4B * 4;
      d[0] = f2tf(px1.x); d[1] = f2tf(px1.y); d[2] = f2tf(px1.z); d[3] = f2tf(px1.w);
#pragma unroll
      for (int it = 0; it < 6; it++) {
        unsigned* dw = ws + wn[it] * PJ_PAD + wc4[it] * 4;
        dw[0] = f2tf(pw[it].x); dw[1] = f2tf(pw[it].y);
        dw[2] = f2tf(pw[it].z); dw[3] = f2tf(pw[it].w);
      }
    }
    __syncthreads();
    // issue next chunk's loads (latency hidden under the mma phase)
    if (kb + 32 < C) {
      px0 = *(const float4*)(xsrcA + kb + 32);
      px1 = *(const float4*)(xsrcB + kb + 32);
#pragma unroll
      for (int it = 0; it < 6; it++)
        pw[it] = *(const float4*)(wsrc[it] + kb + 32);
    }
    // compute on current chunk
#pragma unroll
    for (int kk = 0; kk < 4; kk++) {
      unsigned a0 = xs[(rw + g) * PJ_PAD + 8 * kk + tig];
      unsigned a1 = xs[(rw + g + 8) * PJ_PAD + 8 * kk + tig];
      unsigned a2 = xs[(rw + g) * PJ_PAD + 8 * kk + 4 + tig];
      unsigned a3 = xs[(rw + g + 8) * PJ_PAD + 8 * kk + 4 + tig];
#pragma unroll
      for (int j = 0; j < 12; j++) {
        unsigned b0 = ws[(cw + 8 * j + g) * PJ_PAD + 8 * kk + tig];
        unsigned b1 = ws[(cw + 8 * j + g) * PJ_PAD + 8 * kk + 4 + tig];
        mma_tf32(c[j], a0, a1, a2, a3, b0, b1);
      }
    }
  }

  // epilogue: tf32 bits; q (sel==1) pre-scaled by C^-0.5 = 1/32
  unsigned* outp[3] = {g_k, g_q, g_v};
#pragma unroll
  for (int j = 0; j < 12; j++) {
    int n = cw + 8 * j + 2 * tig;
    int sel = n >> 6, h = n & 63;
    float sc = (sel == 1) ? 0.03125f : 1.0f;
    unsigned* d0 = outp[sel] + ((size_t)b * T + row0 + rw + g) * H + h;
    unsigned* d1 = outp[sel] + ((size_t)b * T + row0 + rw + g + 8) * H + h;
    d0[0] = f2tf(c[j][0] * sc); d0[1] = f2tf(c[j][1] * sc);
    d1[0] = f2tf(c[j][2] * sc); d1[1] = f2tf(c[j][3] * sc);
  }
}

// ---------------------------------------------------------------------------
// Split-KV flash attention with tf32 mma. 128 threads / 4 warps; warp w owns
// S rows [w*16, w*16+16) -> softmax fully warp-local. P aliases K smem.
// (unchanged from R5)
// ---------------------------------------------------------------------------
__global__ __launch_bounds__(128) void attn_part_kernel() {
  const int qt = (T / 64 - 1) - blockIdx.x;
  const int chunk = blockIdx.y;
  const int b = blockIdx.z;
  const int sb_begin = chunk * CHUNK_TILES;
  const int sb_end = min(sb_begin + CHUNK_TILES, qt + 1);
  if (sb_begin > qt) return;  // uniform exit before any barrier

  __shared__ unsigned sQ[64 * 64];
  __shared__ unsigned sKP[64 * 64];  // K tile, then P tile
  __shared__ unsigned sV[64 * 64];
  const int tid = threadIdx.x;
  const int w = tid >> 5, lane = tid & 31, g = lane >> 2, tig = lane & 3;
  const int rw = w * 16;
  const int q0 = qt * 64;

  // stage Q (already tf32 bits, already scaled)
  const unsigned* qg = g_q + ((size_t)b * T + q0) * H;
#pragma unroll
  for (int i = tid; i < 1024; i += 128) {
    int row = i >> 4, c4 = i & 15;
    *(uint4*)(sQ + row * 64 + ((c4 ^ (row & 7)) << 2)) =
        *(const uint4*)(qg + row * 64 + c4 * 4);
  }

  float m0 = -1e30f, m1 = -1e30f, l0 = 0.f, l1 = 0.f;
  float o[8][4];
#pragma unroll
  for (int j = 0; j < 8; j++)
#pragma unroll
    for (int e = 0; e < 4; e++) o[j][e] = 0.f;
  __syncthreads();

  for (int sb = sb_begin; sb < sb_end; sb++) {
    const unsigned* kg = g_k + ((size_t)b * T + sb * 64) * H;
    const unsigned* vg = g_v + ((size_t)b * T + sb * 64) * H;
#pragma unroll
    for (int i = tid; i < 1024; i += 128) {
      int row = i >> 4, c4 = i & 15;
      int d = row * 64 + ((c4 ^ (row & 7)) << 2);
      *(uint4*)(sKP + d) = *(const uint4*)(kg + row * 64 + c4 * 4);
      *(uint4*)(sV + d) = *(const uint4*)(vg + row * 64 + c4 * 4);
    }
    __syncthreads();

    // S = Q K^T (q pre-scaled)
    float s[8][4];
#pragma unroll
    for (int j = 0; j < 8; j++)
#pragma unroll
      for (int e = 0; e < 4; e++) s[j][e] = 0.f;
#pragma unroll
    for (int kk = 0; kk < 8; kk++) {
      unsigned a0 = sQ[(rw + g) * 64 + (((2 * kk) ^ g) << 2 | tig)];
      unsigned a1 = sQ[(rw + g + 8) * 64 + (((2 * kk) ^ g) << 2 | tig)];
      unsigned a2 = sQ[(rw + g) * 64 + (((2 * kk + 1) ^ g) << 2 | tig)];
      unsigned a3 = sQ[(rw + g + 8) * 64 + (((2 * kk + 1) ^ g) << 2 | tig)];
#pragma unroll
      for (int j = 0; j < 8; j++) {
        unsigned b0 = sKP[(8 * j + g) * 64 + (((2 * kk) ^ g) << 2 | tig)];
        unsigned b1 = sKP[(8 * j + g) * 64 + (((2 * kk + 1) ^ g) << 2 | tig)];
        mma_tf32(s[j], a0, a1, a2, a3, b0, b1);
      }
    }

    // causal mask on diagonal tile
    const int qrow0 = q0 + rw + g, qrow1 = qrow0 + 8;
    if (sb == qt) {
#pragma unroll
      for (int j = 0; j < 8; j++) {
        int c0 = sb * 64 + 8 * j + 2 * tig;
        if (c0 > qrow0) s[j][0] = -1e30f;
        if (c0 + 1 > qrow0) s[j][1] = -1e30f;
        if (c0 > qrow1) s[j][2] = -1e30f;
        if (c0 + 1 > qrow1) s[j][3] = -1e30f;
      }
    }

    // online softmax, rows qrow0 (s[.][0,1]) and qrow1 (s[.][2,3])
    float mx0 = -1e30f, mx1 = -1e30f;
#pragma unroll
    for (int j = 0; j < 8; j++) {
      mx0 = fmaxf(mx0, fmaxf(s[j][0], s[j][1]));
      mx1 = fmaxf(mx1, fmaxf(s[j][2], s[j][3]));
    }
#pragma unroll
    for (int off = 1; off <= 2; off <<= 1) {
      mx0 = fmaxf(mx0, __shfl_xor_sync(0xffffffffu, mx0, off));
      mx1 = fmaxf(mx1, __shfl_xor_sync(0xffffffffu, mx1, off));
    }
    float mn0 = fmaxf(m0, mx0), mn1 = fmaxf(m1, mx1);
    float al0 = __expf(m0 - mn0), al1 = __expf(m1 - mn1);
    m0 = mn0; m1 = mn1;
    float rs0 = 0.f, rs1 = 0.f;
#pragma unroll
    for (int j = 0; j < 8; j++) {
      s[j][0] = __expf(s[j][0] - mn0); rs0 += s[j][0];
      s[j][1] = __expf(s[j][1] - mn0); rs0 += s[j][1];
      s[j][2] = __expf(s[j][2] - mn1); rs1 += s[j][2];
      s[j][3] = __expf(s[j][3] - mn1); rs1 += s[j][3];
    }
#pragma unroll
    for (int off = 1; off <= 2; off <<= 1) {
      rs0 += __shfl_xor_sync(0xffffffffu, rs0, off);
      rs1 += __shfl_xor_sync(0xffffffffu, rs1, off);
    }
    l0 = l0 * al0 + rs0;
    l1 = l1 * al1 + rs1;
#pragma unroll
    for (int j = 0; j < 8; j++) {
      o[j][0] *= al0; o[j][1] *= al0;
      o[j][2] *= al1; o[j][3] *= al1;
    }
    __syncthreads();  // everyone done reading sKP as K

    // P -> sKP (tf32 bits), row-major [qrow][key]
#pragma unroll
    for (int j = 0; j < 8; j++) {
      int cc = 8 * j + 2 * tig;
      sKP[(rw + g) * 64 + swz(cc, g)] = f2tf(s[j][0]);
      sKP[(rw + g) * 64 + swz(cc + 1, g)] = f2tf(s[j][1]);
      sKP[(rw + g + 8) * 64 + swz(cc, g)] = f2tf(s[j][2]);
      sKP[(rw + g + 8) * 64 + swz(cc + 1, g)] = f2tf(s[j][3]);
    }
    __syncthreads();

    // O += P V
#pragma unroll
    for (int kk = 0; kk < 8; kk++) {
      int k0 = 8 * kk;
      unsigned a0 = sKP[(rw + g) * 64 + (((2 * kk) ^ g) << 2 | tig)];
      unsigned a1 = sKP[(rw + g + 8) * 64 + (((2 * kk) ^ g) << 2 | tig)];
      unsigned a2 = sKP[(rw + g) * 64 + (((2 * kk + 1) ^ g) << 2 | tig)];
      unsigned a3 = sKP[(rw + g + 8) * 64 + (((2 * kk + 1) ^ g) << 2 | tig)];
#pragma unroll
      for (int j = 0; j < 8; j++) {
        unsigned b0 = sV[(k0 + tig) * 64 + swz(8 * j + g, k0 + tig)];
        unsigned b1 = sV[(k0 + tig + 4) * 64 + swz(8 * j + g, k0 + tig + 4)];
        mma_tf32(o[j], a0, a1, a2, a3, b0, b1);
      }
    }
    __syncthreads();  // before next staging overwrites sKP/sV
  }

  // write unnormalized partial
  const size_t pbase = ((size_t)b * NCHUNK + chunk) * T + q0;
  float* op = g_opart + pbase * H;
#pragma unroll
  for (int j = 0; j < 8; j++) {
    int cc = 8 * j + 2 * tig;
    *(float2*)&op[(size_t)(rw + g) * H + cc] = make_float2(o[j][0], o[j][1]);
    *(float2*)&op[(size_t)(rw + g + 8) * H + cc] = make_float2(o[j][2], o[j][3]);
  }
  if (tig == 0) {
    g_mpart[pbase + rw + g] = m0;
    g_lpart[pbase + rw + g] = l0;
    g_mpart[pbase + rw + g + 8] = m1;
    g_lpart[pbase + rw + g + 8] = l1;
  }
}

// ---------------------------------------------------------------------------
// Reduce partials: out[b,t,h] = sum_i e^{m_i-M} O_i / sum_i e^{m_i-M} l_i
// ---------------------------------------------------------------------------
__global__ __launch_bounds__(256) void attn_reduce_kernel(float* __restrict__ out) {
  const size_t idx = (size_t)blockIdx.x * 256 + threadIdx.x;
  const int h = idx & (H - 1);
  const size_t bt = idx >> 6;
  const int t = (int)(bt & (T - 1));
  const int b = (int)(bt >> 12);
  const int qt = t >> 6;
  const int nch = (qt + CHUNK_TILES) / CHUNK_TILES;

  float mv[NCHUNK], lv[NCHUNK];
  float M = -1e30f;
#pragma unroll
  for (int c = 0; c < NCHUNK; c++) {
    if (c < nch) {
      size_t pb = ((size_t)b * NCHUNK + c) * T + t;
      mv[c] = g_mpart[pb];
      lv[c] = g_lpart[pb];
      M = fmaxf(M, mv[c]);
    }
  }
  float Osum = 0.f, Lsum = 0.f;
#pragma unroll
  for (int c = 0; c < NCHUNK; c++) {
    if (c < nch) {
      float ww = __expf(mv[c] - M);
      size_t pb = ((size_t)b * NCHUNK + c) * T + t;
      Osum += ww * g_opart[pb * H + h];
      Lsum += ww * lv[c];
    }
  }
  out[idx] = Osum / Lsum;
}

extern "C" void kernel_launch(void* const* d_in, const int* in_sizes, int n_in,
                              void* d_out, int out_size) {
  (void)in_sizes; (void)n_in; (void)out_size;
  const float* x  = (const float*)d_in[0];
  const float* Wk = (const float*)d_in[1];
  const float* Wq = (const float*)d_in[2];
  const float* Wv = (const float*)d_in[3];
  float* out = (float*)d_out;

  dim3 pgrid(T / 64, B);
  proj_kernel<<<pgrid, 256>>>(x, Wk, Wq, Wv);
  dim3 agrid(T / 64, NCHUNK, B);
  attn_part_kernel<<<agrid, 128>>>();
  attn_reduce_kernel<<<(B * T * H) / 256, 256>>>(out);
}